// round 11
// baseline (speedup 1.0000x reference)
#include <cuda_runtime.h>
#include <math.h>
#include <stdint.h>

// Shapes (hardcoded for this problem instance)
#define BB   2
#define HH   16
#define SS   2048
#define DD   128
#define MM   4096          // memories per head
#define QQ   4096          // B*S queries per head

#define TQ   128           // query tile per CTA
#define TM   64            // memory tile per iteration (double-buffered)
#define NTHREADS 256
#define NT   (MM / TM)     // 64 tiles
#define SSTR 68            // sims row stride

// Scratch: normalized TRANSPOSED [h][d][*] for contiguous cp.async tiles
__device__ float g_qt[HH * DD * QQ];
__device__ float g_kt[HH * DD * MM];

#define CP16(dst, src) \
    asm volatile("cp.async.cg.shared.global [%0], [%1], 16;" :: "r"(dst), "l"(src))
#define CP_COMMIT() asm volatile("cp.async.commit_group;" ::: "memory")
#define CP_WAIT1()  asm volatile("cp.async.wait_group 1;" ::: "memory")
#define CP_WAIT0()  asm volatile("cp.async.wait_group 0;" ::: "memory")

__device__ __forceinline__ uint32_t smem_u32(const void* p) {
    uint32_t a;
    asm("{ .reg .u64 t; cvta.to.shared.u64 t, %1; cvt.u32.u64 %0, t; }" : "=r"(a) : "l"(p));
    return a;
}

// ---------------------------------------------------------------------------
// Norm + transpose kernels: block = (h, 32-row tile). Normalize rows (same
// arithmetic order as the R1 canary), stage in padded smem, write transposed
// coalesced.
// ---------------------------------------------------------------------------
__global__ void normT_k_kernel(const float* __restrict__ km) {
    __shared__ float tile[32][129];
    const int h  = blockIdx.y;
    const int mt = blockIdx.x;          // 32-row tile of memories
    const int tid = threadIdx.x;
    const int w = tid >> 5, l = tid & 31;

    #pragma unroll
    for (int rr = 0; rr < 4; ++rr) {
        const int row = w * 4 + rr;     // 0..31
        const size_t grow = (size_t)(h * MM + mt * 32 + row);
        float4 v = __ldg(((const float4*)(km + grow * DD)) + l);
        float ss = v.x * v.x + v.y * v.y + v.z * v.z + v.w * v.w;
        #pragma unroll
        for (int o = 16; o > 0; o >>= 1) ss += __shfl_xor_sync(0xffffffffu, ss, o);
        float inv = 1.0f / fmaxf(sqrtf(ss), 1e-11f);
        tile[row][l * 4 + 0] = v.x * inv;
        tile[row][l * 4 + 1] = v.y * inv;
        tile[row][l * 4 + 2] = v.z * inv;
        tile[row][l * 4 + 3] = v.w * inv;
    }
    __syncthreads();
    #pragma unroll
    for (int i = 0; i < 16; ++i) {
        const int idx = i * 256 + tid;
        const int d = idx >> 5, mloc = idx & 31;
        g_kt[((size_t)(h * DD + d)) * MM + mt * 32 + mloc] = tile[mloc][d];
    }
}

__global__ void normT_q_kernel(const float* __restrict__ query) {
    __shared__ float tile[32][129];
    const int h  = blockIdx.y;
    const int qt = blockIdx.x;          // 32-row tile of queries (q' = b*SS+s)
    const int tid = threadIdx.x;
    const int w = tid >> 5, l = tid & 31;

    #pragma unroll
    for (int rr = 0; rr < 4; ++rr) {
        const int row = w * 4 + rr;
        const int qp  = qt * 32 + row;         // 0..4095
        const int b   = qp >> 11;
        const int s   = qp & (SS - 1);
        const size_t grow = (size_t)((b * HH + h) * SS + s);
        float4 v = __ldg(((const float4*)(query + grow * DD)) + l);
        float ss = v.x * v.x + v.y * v.y + v.z * v.z + v.w * v.w;
        #pragma unroll
        for (int o = 16; o > 0; o >>= 1) ss += __shfl_xor_sync(0xffffffffu, ss, o);
        float inv = 1.0f / fmaxf(sqrtf(ss), 1e-11f);
        tile[row][l * 4 + 0] = v.x * inv;
        tile[row][l * 4 + 1] = v.y * inv;
        tile[row][l * 4 + 2] = v.z * inv;
        tile[row][l * 4 + 3] = v.w * inv;
    }
    __syncthreads();
    #pragma unroll
    for (int i = 0; i < 16; ++i) {
        const int idx = i * 256 + tid;
        const int d = idx >> 5, qloc = idx & 31;
        g_qt[((size_t)(h * DD + d)) * QQ + qt * 32 + qloc] = tile[qloc][d];
    }
}

// Register-resident top-16 insert (static indices after unroll -> no spill)
__device__ __forceinline__ void insert16(float v, int idx,
                                         float tv[16], int ti[16],
                                         float& tmin, int& pmin) {
    #pragma unroll
    for (int j = 0; j < 16; ++j) {
        if (j == pmin) { tv[j] = v; ti[j] = idx; }
    }
    tmin = tv[0]; pmin = 0;
    #pragma unroll
    for (int j = 1; j < 16; ++j) {
        if (tv[j] < tmin) { tmin = tv[j]; pmin = j; }
    }
}

// ---------------------------------------------------------------------------
// Fused kernel: per (head, 128-query tile), 64 double-buffered 64-col K tiles.
// cp.async pipeline: at top of iter t, K[t] is complete and K[t+1] in flight;
// after the staging sync we issue K[t+2] into the buffer GEMM just vacated.
// SMEM (floats): Qs[128][128] @0 (64KB), Kb[2][128][64] @16384 (2x32KB),
//                sims[128][SSTR] @32768 (34KB)
// ---------------------------------------------------------------------------
__global__ void __launch_bounds__(NTHREADS, 1)
fused_knn_kernel(const float* __restrict__ vmem,
                 const float* __restrict__ outputs,
                 const float* __restrict__ gate,
                 float* __restrict__ out) {
    extern __shared__ float sm[];
    float* Qs = sm;                  // [d][q] stride 128
    float* Kb[2] = {sm + 16384, sm + 24576};   // [d][m] stride 64
    float* Ss = sm + 32768;          // [q][m] stride SSTR

    const uint32_t sb = smem_u32(sm);
    const int h     = blockIdx.y;
    const int qbase = blockIdx.x * TQ;
    const int tid   = threadIdx.x;
    const int ty    = tid >> 4;      // 0..15: rows ty*8..ty*8+7
    const int tx    = tid & 15;      // 0..15: cols tx*4..tx*4+3
    const int srow  = tid >> 1;      // selection row 0..127
    const int spart = tid & 1;       // selection part (cols 0-31 / 32-63)

    const float* qh = g_qt + (size_t)h * DD * QQ;
    const float* kh = g_kt + (size_t)h * DD * MM;

    // Prologue: Q tile + K0 (group 0), K1 (group 1)
    #pragma unroll
    for (int i = 0; i < 16; ++i) {           // 64KB Q
        const int c = i * 256 + tid;         // 16B chunk
        const int d = c >> 5, qo = (c & 31) << 2;
        CP16(sb + (d * 128 + qo) * 4, qh + (size_t)d * QQ + qbase + qo);
    }
    #pragma unroll
    for (int i = 0; i < 8; ++i) {            // 32KB K0
        const int c = i * 256 + tid;
        const int d = c >> 4, mo = (c & 15) << 2;
        CP16(sb + (16384 + d * 64 + mo) * 4, kh + (size_t)d * MM + mo);
    }
    CP_COMMIT();
    #pragma unroll
    for (int i = 0; i < 8; ++i) {            // 32KB K1
        const int c = i * 256 + tid;
        const int d = c >> 4, mo = (c & 15) << 2;
        CP16(sb + (24576 + d * 64 + mo) * 4, kh + (size_t)d * MM + TM + mo);
    }
    CP_COMMIT();

    // top-16 state (registers)
    float tv[16]; int ti[16];
    #pragma unroll
    for (int j = 0; j < 16; ++j) { tv[j] = -1e30f; ti[j] = 0; }
    float tmin = -1e30f; int pmin = 0;

    for (int t = 0; t < NT; ++t) {
        if (t + 1 < NT) { CP_WAIT1(); } else { CP_WAIT0(); }
        __syncthreads();             // K[t] (and Q) visible; prev sims consumed

        const float* Kbuf = Kb[t & 1];
        float acc[8][4];
        #pragma unroll
        for (int i = 0; i < 8; ++i)
            #pragma unroll
            for (int j = 0; j < 4; ++j) acc[i][j] = 0.0f;

        #pragma unroll 4
        for (int kk = 0; kk < 128; ++kk) {
            const float4 a0 = *(const float4*)&Qs[kk * 128 + ty * 8];
            const float4 a1 = *(const float4*)&Qs[kk * 128 + ty * 8 + 4];
            const float4 b  = *(const float4*)&Kbuf[kk * 64 + tx * 4];
            const float a[8] = {a0.x, a0.y, a0.z, a0.w, a1.x, a1.y, a1.z, a1.w};
            #pragma unroll
            for (int i = 0; i < 8; ++i) {
                acc[i][0] += a[i] * b.x;
                acc[i][1] += a[i] * b.y;
                acc[i][2] += a[i] * b.z;
                acc[i][3] += a[i] * b.w;
            }
        }

        // stage sims: row ty*8+i, cols tx*4..+3 (STS.128, ~2-way)
        #pragma unroll
        for (int i = 0; i < 8; ++i)
            *(float4*)&Ss[(ty * 8 + i) * SSTR + tx * 4] =
                make_float4(acc[i][0], acc[i][1], acc[i][2], acc[i][3]);
        __syncthreads();             // sims ready; K[t] fully consumed

        // refill the vacated buffer with K[t+2]; DMA overlaps selection + next GEMM
        if (t + 2 < NT) {
            #pragma unroll
            for (int i = 0; i < 8; ++i) {
                const int c = i * 256 + tid;
                const int d = c >> 4, mo = (c & 15) << 2;
                CP16(sb + ((t & 1 ? 24576 : 16384) + d * 64 + mo) * 4,
                     kh + (size_t)d * MM + (t + 2) * TM + mo);
            }
            CP_COMMIT();
        }

        // selection: thread (srow, spart) scans 32 candidates (float4)
        const float4* sp = (const float4*)(Ss + srow * SSTR + spart * 32);
        const int base = t * TM + spart * 32;
        #pragma unroll
        for (int c4 = 0; c4 < 8; ++c4) {
            float4 v = sp[c4];
            int bi = base + c4 * 4;
            if (v.x > tmin) insert16(v.x, bi + 0, tv, ti, tmin, pmin);
            if (v.y > tmin) insert16(v.y, bi + 1, tv, ti, tmin, pmin);
            if (v.z > tmin) insert16(v.z, bi + 2, tv, ti, tmin, pmin);
            if (v.w > tmin) insert16(v.w, bi + 3, tv, ti, tmin, pmin);
        }
    }

    // ---- merge the two part-top-16s per row ----
    __syncthreads();
    float* MV = Kb[0];                    // 128*32 floats (fits in Kb0)
    int*   MI = (int*)(Kb[0] + 4096);     // 128*32 ints
    {
        int mb = srow * 32 + spart * 16;
        #pragma unroll
        for (int j = 0; j < 16; ++j) { MV[mb + j] = tv[j]; MI[mb + j] = ti[j]; }
    }
    __syncthreads();

    float* FV = Qs;                       // 128*16 floats
    int*   FI = (int*)(Qs + 2048);        // 128*16 ints
    if (tid < 128) {
        #pragma unroll
        for (int j = 0; j < 16; ++j) { tv[j] = -1e30f; ti[j] = 0; }
        tmin = -1e30f; pmin = 0;
        #pragma unroll 2
        for (int c = 0; c < 32; ++c) {
            float v = MV[tid * 32 + c];
            if (v > tmin) insert16(v, MI[tid * 32 + c], tv, ti, tmin, pmin);
        }
        #pragma unroll
        for (int j = 0; j < 16; ++j) { FV[tid * 16 + j] = tv[j]; FI[tid * 16 + j] = ti[j]; }
    }
    __syncthreads();

    // ---- weighted value gather + gated blend ----
    const int row = tid >> 1;             // 0..127
    const int dh  = (tid & 1) << 6;       // 0 or 64
    float accd[64];
    #pragma unroll
    for (int u = 0; u < 64; ++u) accd[u] = 0.0f;

    const float* vh = vmem + (size_t)h * MM * DD;
    for (int j = 0; j < 16; ++j) {
        float sc = FV[row * 16 + j];
        int   ix = FI[row * 16 + j];
        const float4* vp = (const float4*)(vh + (size_t)ix * DD + dh);
        #pragma unroll
        for (int u = 0; u < 16; ++u) {
            float4 w = __ldg(vp + u);
            accd[4 * u + 0] += sc * w.x;
            accd[4 * u + 1] += sc * w.y;
            accd[4 * u + 2] += sc * w.z;
            accd[4 * u + 3] += sc * w.w;
        }
    }

    // Output flat index == wm flat index (raw reshape); gate head from out layout
    size_t l = ((size_t)(h * QQ + qbase + row)) * DD + dh;
    int hout = (int)((l >> 18) & (HH - 1));     // S*D = 2^18
    float gg = 1.0f / (1.0f + expf(-__ldg(gate + hout)));
    float og = 1.0f - gg;

    const float4* op = (const float4*)(outputs + l);
    float4*       wp = (float4*)(out + l);
    #pragma unroll
    for (int u = 0; u < 16; ++u) {
        float4 o = __ldg(op + u);
        float4 r;
        r.x = gg * accd[4 * u + 0] + og * o.x;
        r.y = gg * accd[4 * u + 1] + og * o.y;
        r.z = gg * accd[4 * u + 2] + og * o.z;
        r.w = gg * accd[4 * u + 3] + og * o.w;
        wp[u] = r;
    }
}

// ---------------------------------------------------------------------------
extern "C" void kernel_launch(void* const* d_in, const int* in_sizes, int n_in,
                              void* d_out, int out_size) {
    // metadata order: inputs, query, key, value, outputs, gate, key_memories, value_memories
    const float* query   = (const float*)d_in[1];
    const float* outputs = (const float*)d_in[4];
    const float* gate    = (const float*)d_in[5];
    const float* kmem    = (const float*)d_in[6];
    const float* vmem    = (const float*)d_in[7];
    float* out = (float*)d_out;

    const int smem_bytes = (32768 + 128 * SSTR) * (int)sizeof(float);  // 165888
    cudaFuncSetAttribute(fused_knn_kernel,
                         cudaFuncAttributeMaxDynamicSharedMemorySize, smem_bytes);

    dim3 gk(MM / 32, HH);
    dim3 gq(QQ / 32, HH);
    normT_k_kernel<<<gk, 256>>>(kmem);
    normT_q_kernel<<<gq, 256>>>(query);

    dim3 grid(QQ / TQ, HH);  // (32, 16)
    fused_knn_kernel<<<grid, NTHREADS, smem_bytes>>>(vmem, outputs, gate, out);
}

// round 12
// speedup vs baseline: 1.8412x; 1.8412x over previous
#include <cuda_runtime.h>
#include <math.h>

// Shapes (hardcoded for this problem instance)
#define BB   2
#define HH   16
#define SS   2048
#define DD   128
#define MM   4096          // memories per head
#define QQ   4096          // B*S queries per head

#define TQ   64            // query tile per CTA (occ-2 sizing)
#define TM   128           // memory tile per iteration
#define NTHREADS 128

// SMEM (floats): Qs [d][q] 128x64 @0 (32KB), Ks [d][m] 128x128 @8192 (64KB)
// sims alias into Ks head: 64 rows x stride 129 = 8256 floats (33KB <= 64KB)
#define SMEM_FLOATS (8192 + 16384)

// Scratch: normalized queries and keys (32 MB each)
__device__ float g_qn[HH * QQ * DD];
__device__ float g_kn[HH * MM * DD];

// ---------------------------------------------------------------------------
// Normalization kernels: one warp per 128-float row (identical to R1)
// ---------------------------------------------------------------------------
__global__ void norm_k_kernel(const float* __restrict__ km) {
    int wid  = (blockIdx.x * blockDim.x + threadIdx.x) >> 5;
    int lane = threadIdx.x & 31;
    if (wid >= HH * MM) return;
    float4 v = __ldg(((const float4*)(km + (size_t)wid * DD)) + lane);
    float ss = v.x * v.x + v.y * v.y + v.z * v.z + v.w * v.w;
    #pragma unroll
    for (int o = 16; o > 0; o >>= 1) ss += __shfl_xor_sync(0xffffffffu, ss, o);
    float inv = 1.0f / fmaxf(sqrtf(ss), 1e-11f);
    float4 r = make_float4(v.x * inv, v.y * inv, v.z * inv, v.w * inv);
    ((float4*)(g_kn + (size_t)wid * DD))[lane] = r;
}

__global__ void norm_q_kernel(const float* __restrict__ query) {
    int wid  = (blockIdx.x * blockDim.x + threadIdx.x) >> 5;
    int lane = threadIdx.x & 31;
    if (wid >= HH * QQ) return;
    int h = wid >> 12;          // / 4096
    int q = wid & (QQ - 1);
    int b = q >> 11;            // / 2048
    int s = q & (SS - 1);
    size_t src = ((size_t)((b * HH + h) * SS + s)) * DD;
    float4 v = __ldg(((const float4*)(query + src)) + lane);
    float ss = v.x * v.x + v.y * v.y + v.z * v.z + v.w * v.w;
    #pragma unroll
    for (int o = 16; o > 0; o >>= 1) ss += __shfl_xor_sync(0xffffffffu, ss, o);
    float inv = 1.0f / fmaxf(sqrtf(ss), 1e-11f);
    float4 r = make_float4(v.x * inv, v.y * inv, v.z * inv, v.w * inv);
    ((float4*)(g_qn + (size_t)wid * DD))[lane] = r;
}

// ---------------------------------------------------------------------------
// K tile loader (128x128), R1 traversal at 128 threads (32 float4/thread):
// (row, d) -> dst[d*128 + ((row>>2 ^ ((d>>2)&7))<<2) + (row&3)]
// ---------------------------------------------------------------------------
__device__ __forceinline__ void load_k_tile(const float* __restrict__ src,
                                            float* __restrict__ dst, int tid) {
    #pragma unroll
    for (int i = 0; i < 32; ++i) {
        int f   = i * 128 + tid;        // float4 index 0..4095
        int row = f >> 5;               // 0..127
        int d0  = (f & 31) << 2;        // 0..124
        float4 v = __ldg((const float4*)(src + (size_t)row * DD + d0));
        float vv[4] = {v.x, v.y, v.z, v.w};
        int cg = row >> 2;
        int rl = row & 3;
        #pragma unroll
        for (int j = 0; j < 4; ++j) {
            int d = d0 + j;
            dst[d * 128 + (((cg) ^ ((d >> 2) & 7)) << 2) + rl] = vv[j];
        }
    }
}

// Q tile loader (64x128 -> [d][q] width 64), 16 row-groups, swizzle mod 16:
// (row, d) -> dst[d*64 + ((row>>2 ^ ((d>>2)&15))<<2) + (row&3)]
__device__ __forceinline__ void load_q_tile(const float* __restrict__ src,
                                            float* __restrict__ dst, int tid) {
    #pragma unroll
    for (int i = 0; i < 16; ++i) {
        int f   = i * 128 + tid;        // float4 index 0..2047
        int row = f >> 5;               // 0..63
        int d0  = (f & 31) << 2;        // 0..124
        float4 v = __ldg((const float4*)(src + (size_t)row * DD + d0));
        float vv[4] = {v.x, v.y, v.z, v.w};
        int cg = row >> 2;
        int rl = row & 3;
        #pragma unroll
        for (int j = 0; j < 4; ++j) {
            int d = d0 + j;
            dst[d * 64 + (((cg) ^ ((d >> 2) & 15)) << 2) + rl] = vv[j];
        }
    }
}

// Register-resident top-16 insert (static indices after unroll -> no spill)
__device__ __forceinline__ void insert16(float v, int idx,
                                         float tv[16], int ti[16],
                                         float& tmin, int& pmin) {
    #pragma unroll
    for (int j = 0; j < 16; ++j) {
        if (j == pmin) { tv[j] = v; ti[j] = idx; }
    }
    tmin = tv[0]; pmin = 0;
    #pragma unroll
    for (int j = 1; j < 16; ++j) {
        if (tv[j] < tmin) { tmin = tv[j]; pmin = j; }
    }
}

// ---------------------------------------------------------------------------
// Fused kernel (R1 inner loop, TQ=64, occ 2): per (head, 64-query tile):
//   loop 32 tiles: load K -> GEMM (8x8 acc) -> sync -> stage sims into Ks head
//   (stride 129) -> sync -> selection.  Then merge, gather, blend, write.
// Thread (ty, tx): ty=tid>>4 (0..7) rows ty*8..+7; tx=tid&15 cols tx*8..+7.
// ---------------------------------------------------------------------------
__global__ void __launch_bounds__(NTHREADS, 2)
fused_knn_kernel(const float* __restrict__ vmem,
                 const float* __restrict__ outputs,
                 const float* __restrict__ gate,
                 float* __restrict__ out) {
    extern __shared__ float sm[];
    float* Qs = sm;                 // 8192 floats
    float* Ks = sm + 8192;          // 16384 floats (sims alias its head)
    float* Ss = Ks;                 // 64 x 129 sims

    const int h     = blockIdx.y;
    const int qbase = blockIdx.x * TQ;
    const int tid   = threadIdx.x;
    const int ty    = tid >> 4;     // 0..7  (rows ty*8..ty*8+7)
    const int tx    = tid & 15;     // 0..15 (cols tx*8..tx*8+7)
    const int srow  = tid >> 1;     // selection row 0..63
    const int shalf = tid & 1;      // selection half (0/1)

    load_q_tile(g_qn + ((size_t)(h * QQ + qbase)) * DD, Qs, tid);

    // top-16 state (registers)
    float tv[16]; int ti[16];
    #pragma unroll
    for (int j = 0; j < 16; ++j) { tv[j] = -1e30f; ti[j] = 0; }
    float tmin = -1e30f; int pmin = 0;

    const float* kh = g_kn + (size_t)h * MM * DD;

    for (int mt = 0; mt < MM; mt += TM) {
        __syncthreads();  // prev selection done with Ss(=Ks); Qs ready (1st)
        load_k_tile(kh + (size_t)mt * DD, Ks, tid);
        __syncthreads();

        float acc[8][8];
        #pragma unroll
        for (int i = 0; i < 8; ++i)
            #pragma unroll
            for (int j = 0; j < 8; ++j) acc[i][j] = 0.0f;

        #pragma unroll 4
        for (int kk = 0; kk < 128; ++kk) {
            int s8  = (kk >> 2) & 7;
            int s16 = (kk >> 2) & 15;
            const float4 a0 = *(const float4*)&Qs[kk * 64  + (((ty * 2)     ^ s16) << 2)];
            const float4 a1 = *(const float4*)&Qs[kk * 64  + (((ty * 2 + 1) ^ s16) << 2)];
            const float4 b0 = *(const float4*)&Ks[kk * 128 + (((tx * 2)     ^ s8)  << 2)];
            const float4 b1 = *(const float4*)&Ks[kk * 128 + (((tx * 2 + 1) ^ s8)  << 2)];
            float a[8] = {a0.x, a0.y, a0.z, a0.w, a1.x, a1.y, a1.z, a1.w};
            float b[8] = {b0.x, b0.y, b0.z, b0.w, b1.x, b1.y, b1.z, b1.w};
            #pragma unroll
            for (int i = 0; i < 8; ++i)
                #pragma unroll
                for (int j = 0; j < 8; ++j) acc[i][j] += a[i] * b[j];
        }
        __syncthreads();  // all GEMM reads of Ks complete before sims overwrite it

        // stage sims into Ks head (stride 129, conflict-free column scans)
        #pragma unroll
        for (int i = 0; i < 8; ++i)
            #pragma unroll
            for (int j = 0; j < 8; ++j)
                Ss[(ty * 8 + i) * 129 + tx * 8 + j] = acc[i][j];
        __syncthreads();

        // selection: thread (srow, shalf) scans 64 candidates
        const float* sp = Ss + srow * 129 + shalf * 64;
        const int base = mt + shalf * 64;
        #pragma unroll 4
        for (int c = 0; c < 64; ++c) {
            float v = sp[c];
            if (v > tmin) insert16(v, base + c, tv, ti, tmin, pmin);
        }
    }

    // ---- merge the two halves per row (scratch in Qs region) ----
    __syncthreads();
    float* MV = Qs;                       // 64*32 floats
    int*   MI = (int*)(Qs + 2048);        // 64*32 ints
    {
        int mb = srow * 32 + shalf * 16;
        #pragma unroll
        for (int j = 0; j < 16; ++j) { MV[mb + j] = tv[j]; MI[mb + j] = ti[j]; }
    }
    __syncthreads();

    float* FV = Qs + 4096;                // 64*16 floats
    int*   FI = (int*)(Qs + 5120);        // 64*16 ints
    if (tid < 64) {
        #pragma unroll
        for (int j = 0; j < 16; ++j) { tv[j] = -1e30f; ti[j] = 0; }
        tmin = -1e30f; pmin = 0;
        #pragma unroll 2
        for (int c = 0; c < 32; ++c) {
            float v = MV[tid * 32 + c];
            if (v > tmin) insert16(v, MI[tid * 32 + c], tv, ti, tmin, pmin);
        }
        #pragma unroll
        for (int j = 0; j < 16; ++j) { FV[tid * 16 + j] = tv[j]; FI[tid * 16 + j] = ti[j]; }
    }
    __syncthreads();

    // ---- weighted value gather + gated blend ----
    const int row = tid >> 1;             // 0..63
    const int dh  = (tid & 1) << 6;       // 0 or 64
    float accd[64];
    #pragma unroll
    for (int t = 0; t < 64; ++t) accd[t] = 0.0f;

    const float* vh = vmem + (size_t)h * MM * DD;
    for (int j = 0; j < 16; ++j) {
        float sc = FV[row * 16 + j];
        int   ix = FI[row * 16 + j];
        const float4* vp = (const float4*)(vh + (size_t)ix * DD + dh);
        #pragma unroll
        for (int t = 0; t < 16; ++t) {
            float4 w = __ldg(vp + t);
            accd[4 * t + 0] += sc * w.x;
            accd[4 * t + 1] += sc * w.y;
            accd[4 * t + 2] += sc * w.z;
            accd[4 * t + 3] += sc * w.w;
        }
    }

    // Output flat index == wm flat index (raw reshape); gate head from out layout
    size_t l = ((size_t)(h * QQ + qbase + row)) * DD + dh;
    int hout = (int)((l >> 18) & (HH - 1));     // S*D = 2^18
    float gg = 1.0f / (1.0f + expf(-__ldg(gate + hout)));
    float og = 1.0f - gg;

    const float4* op = (const float4*)(outputs + l);
    float4*       wp = (float4*)(out + l);
    #pragma unroll
    for (int t = 0; t < 16; ++t) {
        float4 o = __ldg(op + t);
        float4 r;
        r.x = gg * accd[4 * t + 0] + og * o.x;
        r.y = gg * accd[4 * t + 1] + og * o.y;
        r.z = gg * accd[4 * t + 2] + og * o.z;
        r.w = gg * accd[4 * t + 3] + og * o.w;
        wp[t] = r;
    }
}

// ---------------------------------------------------------------------------
extern "C" void kernel_launch(void* const* d_in, const int* in_sizes, int n_in,
                              void* d_out, int out_size) {
    // metadata order: inputs, query, key, value, outputs, gate, key_memories, value_memories
    const float* query   = (const float*)d_in[1];
    const float* outputs = (const float*)d_in[4];
    const float* gate    = (const float*)d_in[5];
    const float* kmem    = (const float*)d_in[6];
    const float* vmem    = (const float*)d_in[7];
    float* out = (float*)d_out;

    const int smem_bytes = SMEM_FLOATS * (int)sizeof(float);  // 98304
    cudaFuncSetAttribute(fused_knn_kernel,
                         cudaFuncAttributeMaxDynamicSharedMemorySize, smem_bytes);

    norm_k_kernel<<<(HH * MM) / 8, 256>>>(kmem);
    norm_q_kernel<<<(HH * QQ) / 8, 256>>>(query);

    dim3 grid(QQ / TQ, HH);  // (64, 16) = 1024 CTAs, 2 per SM
    fused_knn_kernel<<<grid, NTHREADS, smem_bytes>>>(vmem, outputs, gate, out);
}